// round 14
// baseline (speedup 1.0000x reference)
#include <cuda_runtime.h>
#include <cuda_fp16.h>

#define BATCH 32
#define CDIM  256
#define LDIM  1024

// ---------------------------------------------------------------------------
// Global scratch
// q/k packed: [b][m][i], m = c/2, uint2 = (hi2, lo2)
// v/std packed: [b][c][j2] half2 ; P: [b][i][j2] half2
// ---------------------------------------------------------------------------
__device__ uint2    d_qpk[(size_t)BATCH * (CDIM / 2) * LDIM];      // 32 MiB
__device__ uint2    d_kpk[(size_t)BATCH * (CDIM / 2) * LDIM];      // 32 MiB
__device__ unsigned d_vpk[(size_t)BATCH * CDIM * (LDIM / 2)];      // 16 MiB
__device__ unsigned d_spk[(size_t)BATCH * CDIM * (LDIM / 2)];      // 16 MiB
__device__ unsigned d_Ph [(size_t)BATCH * LDIM * (LDIM / 2)];      // 64 MiB

__device__ __forceinline__ unsigned pk2(__half a, __half b) {
    __half2 t = __halves2half2(a, b);
    return *reinterpret_cast<unsigned*>(&t);
}

__device__ __forceinline__ void mma16(float* c,
                                      unsigned a0, unsigned a1, unsigned a2, unsigned a3,
                                      unsigned b0, unsigned b1) {
    asm volatile(
        "mma.sync.aligned.m16n8k16.row.col.f32.f16.f16.f32 "
        "{%0,%1,%2,%3}, {%4,%5,%6,%7}, {%8,%9}, {%0,%1,%2,%3};\n"
        : "+f"(c[0]), "+f"(c[1]), "+f"(c[2]), "+f"(c[3])
        : "r"(a0), "r"(a1), "r"(a2), "r"(a3), "r"(b0), "r"(b1));
}

__device__ __forceinline__ void ldsm4(unsigned& r0, unsigned& r1,
                                      unsigned& r2, unsigned& r3, unsigned a) {
    asm volatile("ldmatrix.sync.aligned.m8n8.x4.shared.b16 {%0,%1,%2,%3}, [%4];"
                 : "=r"(r0), "=r"(r1), "=r"(r2), "=r"(r3) : "r"(a));
}

__device__ __forceinline__ void cp16(unsigned dst, const void* src) {
    asm volatile("cp.async.cg.shared.global [%0], [%1], 16;" :: "r"(dst), "l"(src));
}
__device__ __forceinline__ void cp4(unsigned dst, const void* src) {
    asm volatile("cp.async.ca.shared.global [%0], [%1], 4;" :: "r"(dst), "l"(src));
}
#define CP_COMMIT() asm volatile("cp.async.commit_group;")
#define CP_WAIT(N)  asm volatile("cp.async.wait_group %0;" :: "n"(N))

// ---------------------------------------------------------------------------
// Merged pack kernel (R13, unchanged)
// ---------------------------------------------------------------------------
__global__ void pack_all(const float* __restrict__ q, const float* __restrict__ k,
                         const float* __restrict__ v, const float* __restrict__ sd) {
    int gid = blockIdx.x * 256 + threadIdx.x;

    {
        int b   = gid >> 17;
        int rem = gid & 131071;
        int m   = rem >> 10;
        int i   = rem & 1023;
        size_t src = (size_t)b * CDIM * LDIM + (size_t)(2 * m) * LDIM + i;

        float x0 = q[src], x1 = q[src + LDIM];
        __half h0 = __float2half_rn(x0), h1 = __float2half_rn(x1);
        __half l0 = __float2half_rn(x0 - __half2float(h0));
        __half l1 = __float2half_rn(x1 - __half2float(h1));
        d_qpk[gid] = make_uint2(pk2(h0, h1), pk2(l0, l1));

        float y0 = k[src], y1 = k[src + LDIM];
        __half g0 = __float2half_rn(y0), g1 = __float2half_rn(y1);
        __half m0 = __float2half_rn(y0 - __half2float(g0));
        __half m1 = __float2half_rn(y1 - __half2float(g1));
        d_kpk[gid] = make_uint2(pk2(g0, g1), pk2(m0, m1));
    }

    {
        size_t src = (size_t)gid * 2;
        float2 t = *(const float2*)(v + src);
        d_vpk[gid] = pk2(__float2half_rn(t.x), __float2half_rn(t.y));
        float2 u = *(const float2*)(sd + src);
        d_spk[gid] = pk2(__float2half_rn(u.x), __float2half_rn(u.y));
    }
}

// ---------------------------------------------------------------------------
// Kernel 1: scores (R13 mainloop; adds batch offset b0 + A-ldsm hoisted
// above CP_WAIT — A frags depend only on resident Q).
// ---------------------------------------------------------------------------
#define T1 512
#define SC_QH   0
#define SC_QL   16896
#define SC_KW   33792
#define SC_RED  173056
#define SC_TOTAL 175104

__global__ void __launch_bounds__(T1)
scores_kernel(const float* __restrict__ table, const int* __restrict__ ridx,
              int b0) {
    extern __shared__ unsigned char smraw[];
    const unsigned sbase = (unsigned)__cvta_generic_to_shared(smraw);

    const int b    = blockIdx.y + b0;
    const int i0   = blockIdx.x * 32;
    const int tid  = threadIdx.x;
    const int warp = tid >> 5;
    const int lane = tid & 31;
    const int g    = lane >> 2;
    const int tig  = lane & 3;
    const int j0w  = warp * 64;

    const uint2* gq = d_qpk + (size_t)b * (CDIM / 2) * LDIM;
    const uint2* gk = d_kpk + (size_t)b * (CDIM / 2) * LDIM;

    float acc[2][8][4];
#pragma unroll
    for (int it = 0; it < 2; it++)
#pragma unroll
        for (int jt = 0; jt < 8; jt++)
#pragma unroll
            for (int f = 0; f < 4; f++) acc[it][jt][f] = 0.f;

    // ---- stage full Q once ----
#pragma unroll
    for (int t = 0; t < 8; t++) {
        int idx = tid + t * T1;
        int m   = idx >> 5;
        int ii  = idx & 31;
        const uint2* s = gq + (size_t)m * LDIM + i0 + ii;
        unsigned d = (unsigned)((ii * 132 + m) * 4);
        cp4(sbase + SC_QH + d, &s->x);
        cp4(sbase + SC_QL + d, &s->y);
    }
    CP_COMMIT();

    // ---- per-warp K staging, carried pointer ----
    const int krow = lane >> 2;
    const int kq4  = lane & 3;
    const unsigned wd0 = sbase + SC_KW + warp * (2 * 4352) + krow * 544 + kq4 * 16;
    const unsigned wd1 = wd0 + 4352;
    const uint2* kptr = gk + (size_t)krow * LDIM + j0w + kq4 * 2;

#define SC_STAGEW(PTR, DSTB)                                                  \
    {                                                                         \
        _Pragma("unroll")                                                     \
        for (int t = 0; t < 8; t++)                                           \
            cp16((DSTB) + t * 64, (PTR) + t * 8);                             \
        CP_COMMIT();                                                          \
    }

    SC_STAGEW(kptr, wd0); kptr += 8 * LDIM;
    SC_STAGEW(kptr, wd1); kptr += 8 * LDIM;
    CP_WAIT(2);                           // Q resident
    __syncthreads();                      // the ONLY pre-epilogue barrier

    const unsigned arow = (lane & 15);
    const unsigned acol = (lane >> 4) * 16;
    const uint2* wkb0 = (const uint2*)(smraw + SC_KW + warp * (2 * 4352));
    const uint2* wkb1 = (const uint2*)(smraw + SC_KW + warp * (2 * 4352) + 4352);

    for (int cc = 0; cc < 16; cc++) {
        // A fragments first: independent of pending K groups (hoisted)
        unsigned ah[2][4], al[2][4];
#pragma unroll
        for (int it = 0; it < 2; it++) {
            ldsm4(ah[it][0], ah[it][1], ah[it][2], ah[it][3],
                  sbase + SC_QH + (it * 16 + arow) * 528 + cc * 32 + acol);
            ldsm4(al[it][0], al[it][1], al[it][2], al[it][3],
                  sbase + SC_QL + (it * 16 + arow) * 528 + cc * 32 + acol);
        }

        if (cc < 15) { CP_WAIT(1); } else { CP_WAIT(0); }

        const uint2* wkb = (cc & 1) ? wkb1 : wkb0;
        // jh = 0
        uint2 y0a[4], y1a[4];
#pragma unroll
        for (int j4 = 0; j4 < 4; j4++) {
            int jcol = j4 * 8 + g;
            y0a[j4] = wkb[tig * 68 + jcol];
            y1a[j4] = wkb[(tig + 4) * 68 + jcol];
        }
#pragma unroll
        for (int j4 = 0; j4 < 4; j4++)
#pragma unroll
            for (int it = 0; it < 2; it++)
                mma16(acc[it][j4], ah[it][0], ah[it][1], ah[it][2], ah[it][3],
                      y0a[j4].x, y1a[j4].x);
#pragma unroll
        for (int j4 = 0; j4 < 4; j4++)
#pragma unroll
            for (int it = 0; it < 2; it++)
                mma16(acc[it][j4], ah[it][0], ah[it][1], ah[it][2], ah[it][3],
                      y0a[j4].y, y1a[j4].y);
#pragma unroll
        for (int j4 = 0; j4 < 4; j4++)
#pragma unroll
            for (int it = 0; it < 2; it++)
                mma16(acc[it][j4], al[it][0], al[it][1], al[it][2], al[it][3],
                      y0a[j4].x, y1a[j4].x);

        // jh = 1: reads first, then refill this buffer, then mma
        uint2 y0b[4], y1b[4];
#pragma unroll
        for (int j4 = 0; j4 < 4; j4++) {
            int jcol = 32 + j4 * 8 + g;
            y0b[j4] = wkb[tig * 68 + jcol];
            y1b[j4] = wkb[(tig + 4) * 68 + jcol];
        }
        if (cc + 2 < 16) {
            unsigned dcur = (cc & 1) ? wd1 : wd0;
            SC_STAGEW(kptr, dcur);
            kptr += 8 * LDIM;
        }

#pragma unroll
        for (int j4 = 0; j4 < 4; j4++)
#pragma unroll
            for (int it = 0; it < 2; it++)
                mma16(acc[it][4 + j4], ah[it][0], ah[it][1], ah[it][2], ah[it][3],
                      y0b[j4].x, y1b[j4].x);
#pragma unroll
        for (int j4 = 0; j4 < 4; j4++)
#pragma unroll
            for (int it = 0; it < 2; it++)
                mma16(acc[it][4 + j4], ah[it][0], ah[it][1], ah[it][2], ah[it][3],
                      y0b[j4].y, y1b[j4].y);
#pragma unroll
        for (int j4 = 0; j4 < 4; j4++)
#pragma unroll
            for (int it = 0; it < 2; it++)
                mma16(acc[it][4 + j4], al[it][0], al[it][1], al[it][2], al[it][3],
                      y0b[j4].x, y1b[j4].x);
    }

    float* red = (float*)(smraw + SC_RED);

    // ---- add bias via table[ridx] gather ----
#pragma unroll
    for (int it = 0; it < 2; it++)
#pragma unroll
        for (int rr = 0; rr < 2; rr++) {
            int rowl = it * 16 + g + rr * 8;
            const int* rrow = ridx + (size_t)(i0 + rowl) * LDIM + j0w + 2 * tig;
#pragma unroll
            for (int jt = 0; jt < 8; jt++) {
                int2 rv = *(const int2*)(rrow + jt * 8);
                acc[it][jt][rr * 2]     += __ldg(table + rv.x);
                acc[it][jt][rr * 2 + 1] += __ldg(table + rv.y);
            }
        }

    // ---- row max ----
    float mrow[2][2];
#pragma unroll
    for (int it = 0; it < 2; it++)
#pragma unroll
        for (int rr = 0; rr < 2; rr++) {
            float m = -3.4e38f;
#pragma unroll
            for (int jt = 0; jt < 8; jt++) {
                m = fmaxf(m, acc[it][jt][rr * 2]);
                m = fmaxf(m, acc[it][jt][rr * 2 + 1]);
            }
            m = fmaxf(m, __shfl_xor_sync(0xffffffffu, m, 1));
            m = fmaxf(m, __shfl_xor_sync(0xffffffffu, m, 2));
            if (tig == 0) red[(it * 16 + g + rr * 8) * 16 + warp] = m;
        }
    __syncthreads();
#pragma unroll
    for (int it = 0; it < 2; it++)
#pragma unroll
        for (int rr = 0; rr < 2; rr++) {
            int rowl = it * 16 + g + rr * 8;
            float m = red[rowl * 16];
#pragma unroll
            for (int w = 1; w < 16; w++) m = fmaxf(m, red[rowl * 16 + w]);
            mrow[it][rr] = m;
        }
    __syncthreads();

    // ---- exp + row sum ----
#pragma unroll
    for (int it = 0; it < 2; it++)
#pragma unroll
        for (int rr = 0; rr < 2; rr++) {
            float s = 0.f;
#pragma unroll
            for (int jt = 0; jt < 8; jt++) {
                float p0 = __expf(acc[it][jt][rr * 2]     - mrow[it][rr]);
                float p1 = __expf(acc[it][jt][rr * 2 + 1] - mrow[it][rr]);
                acc[it][jt][rr * 2]     = p0;
                acc[it][jt][rr * 2 + 1] = p1;
                s += p0 + p1;
            }
            s += __shfl_xor_sync(0xffffffffu, s, 1);
            s += __shfl_xor_sync(0xffffffffu, s, 2);
            if (tig == 0) red[(it * 16 + g + rr * 8) * 16 + warp] = s;
        }
    __syncthreads();

    unsigned* Pb = d_Ph + ((size_t)b * LDIM + i0) * (LDIM / 2);
#pragma unroll
    for (int it = 0; it < 2; it++)
#pragma unroll
        for (int rr = 0; rr < 2; rr++) {
            int rowl = it * 16 + g + rr * 8;
            float s = red[rowl * 16];
#pragma unroll
            for (int w = 1; w < 16; w++) s += red[rowl * 16 + w];
            float inv = 1.0f / s;
            unsigned* prow = Pb + (size_t)rowl * (LDIM / 2) + j0w / 2 + tig;
#pragma unroll
            for (int jt = 0; jt < 8; jt++) {
                __half2 h = __floats2half2_rn(acc[it][jt][rr * 2] * inv,
                                              acc[it][jt][rr * 2 + 1] * inv);
                prow[jt * 4] = *reinterpret_cast<unsigned*>(&h);
            }
        }
}

// ---------------------------------------------------------------------------
// Kernel 2: out (R13 version + batch offset b0)
// ---------------------------------------------------------------------------
#define T2  256
#define OSW 36

#define OC_BUFB     ((128 + 64 + 64) * OSW * 4)
#define OC_PS(buf)  ((buf) * OC_BUFB)
#define OC_VS(buf)  (OC_PS(buf) + 128 * OSW * 4)
#define OC_SS(buf)  (OC_PS(buf) + (128 + 64) * OSW * 4)
#define OC_TOTAL    (3 * OC_BUFB)

__global__ void __launch_bounds__(T2, 2)
out_kernel(float* __restrict__ out, int b0) {
    extern __shared__ unsigned char smraw2[];
    const unsigned sbase = (unsigned)__cvta_generic_to_shared(smraw2);

    const int b    = blockIdx.z + b0;
    const int i0   = blockIdx.x * 128;
    const int c0   = blockIdx.y * 64;
    const int tid  = threadIdx.x;
    const int warp = tid >> 5;
    const int lane = tid & 31;
    const int g    = lane >> 2;
    const int tig  = lane & 3;
    const int wi   = warp & 3;
    const int wc   = warp >> 2;

    const unsigned* Pb = d_Ph + ((size_t)b * LDIM + i0) * (LDIM / 2);
    const unsigned* vb = d_vpk + ((size_t)b * CDIM + c0) * (LDIM / 2);
    const unsigned* sb = d_spk + ((size_t)b * CDIM + c0) * (LDIM / 2);

    float aV[2][4][4], aS[2][4][4];
#pragma unroll
    for (int it = 0; it < 2; it++)
#pragma unroll
        for (int nt = 0; nt < 4; nt++)
#pragma unroll
            for (int f = 0; f < 4; f++) { aV[it][nt][f] = 0.f; aS[it][nt][f] = 0.f; }

#define OC_STAGE(JC, BUF)                                                     \
    {                                                                         \
        _Pragma("unroll")                                                     \
        for (int t = 0; t < 4; t++) {                                         \
            int idx  = tid + t * T2;                                          \
            int row  = idx >> 3;                                              \
            int col4 = idx & 7;                                               \
            cp16(sbase + OC_PS(BUF) + row * (OSW * 4) + col4 * 16,            \
                 Pb + (size_t)row * (LDIM / 2) + (JC) * 32 + col4 * 4);       \
        }                                                                     \
        _Pragma("unroll")                                                     \
        for (int t = 0; t < 2; t++) {                                         \
            int idx  = tid + t * T2;                                          \
            int row  = idx >> 3;                                              \
            int col4 = idx & 7;                                               \
            unsigned soff = row * (OSW * 4) + col4 * 16;                      \
            size_t   goff = (size_t)row * (LDIM / 2) + (JC) * 32 + col4 * 4;  \
            cp16(sbase + OC_VS(BUF) + soff, vb + goff);                       \
            cp16(sbase + OC_SS(BUF) + soff, sb + goff);                       \
        }                                                                     \
        CP_COMMIT();                                                          \
    }

    OC_STAGE(0, 0);
    OC_STAGE(1, 1);

    const unsigned a_row = (lane & 15);
    const unsigned a_col = (lane >> 4) * 16;
    const unsigned b_row = ((lane >> 4) & 1) * 8 + (lane & 7);
    const unsigned b_col = ((lane >> 3) & 1) * 16;

    int bufc = 0;
    int bufs = 2;
    for (int jc = 0; jc < 16; jc++) {
        if (jc < 15) { CP_WAIT(1); } else { CP_WAIT(0); }
        __syncthreads();

#pragma unroll
        for (int kb = 0; kb < 4; kb++) {
            unsigned a0[2], a1[2], a2[2], a3[2];
#pragma unroll
            for (int it = 0; it < 2; it++)
                ldsm4(a0[it], a1[it], a2[it], a3[it],
                      sbase + OC_PS(bufc) +
                      (wi * 32 + it * 16 + a_row) * (OSW * 4) + kb * 32 + a_col);

            unsigned bv0[4], bv1[4], bs0[4], bs1[4];
#pragma unroll
            for (int nh = 0; nh < 2; nh++) {
                unsigned roff = (wc * 32 + nh * 16 + b_row) * (OSW * 4) + kb * 32 + b_col;
                ldsm4(bv0[2 * nh], bv1[2 * nh], bv0[2 * nh + 1], bv1[2 * nh + 1],
                      sbase + OC_VS(bufc) + roff);
                ldsm4(bs0[2 * nh], bs1[2 * nh], bs0[2 * nh + 1], bs1[2 * nh + 1],
                      sbase + OC_SS(bufc) + roff);
            }
#pragma unroll
            for (int nt = 0; nt < 4; nt++)
#pragma unroll
                for (int it = 0; it < 2; it++) {
                    mma16(aV[it][nt], a0[it], a1[it], a2[it], a3[it], bv0[nt], bv1[nt]);
                    mma16(aS[it][nt], a0[it], a1[it], a2[it], a3[it], bs0[nt], bs1[nt]);
                }
        }
        if (jc + 2 < 16) OC_STAGE(jc + 2, bufs);
        bufc = (bufc == 2) ? 0 : bufc + 1;
        bufs = (bufs == 2) ? 0 : bufs + 1;
    }

    const size_t base  = (size_t)b * CDIM * LDIM;
    const size_t sdoff = (size_t)BATCH * CDIM * LDIM;
#pragma unroll
    for (int it = 0; it < 2; it++)
#pragma unroll
        for (int nt = 0; nt < 4; nt++)
#pragma unroll
            for (int rr = 0; rr < 2; rr++) {
                int i = i0 + wi * 32 + it * 16 + g + rr * 8;
#pragma unroll
                for (int ff = 0; ff < 2; ff++) {
                    int c = c0 + wc * 32 + nt * 8 + 2 * tig + ff;
                    size_t o = base + (size_t)c * LDIM + i;
                    out[o]         = aV[it][nt][rr * 2 + ff];
                    out[o + sdoff] = aS[it][nt][rr * 2 + ff];
                }
            }
}

// ---------------------------------------------------------------------------
// Launch: 2 batch groups of 16; out(g0) on a second stream overlaps
// scores(g1). Fork/join with events (graph-capture-safe pattern).
// ---------------------------------------------------------------------------
extern "C" void kernel_launch(void* const* d_in, const int* in_sizes, int n_in,
                              void* d_out, int out_size) {
    const float* q     = (const float*)d_in[0];
    const float* k     = (const float*)d_in[1];
    const float* v     = (const float*)d_in[2];
    const float* sd    = (const float*)d_in[3];
    const float* table = (const float*)d_in[4];
    const int*   ridx  = (const int*)d_in[5];
    float* out = (float*)d_out;

    static cudaStream_t s2 = nullptr;
    static cudaEvent_t evA = nullptr, evB = nullptr;
    if (s2 == nullptr) {
        cudaStreamCreateWithFlags(&s2, cudaStreamNonBlocking);
        cudaEventCreateWithFlags(&evA, cudaEventDisableTiming);
        cudaEventCreateWithFlags(&evB, cudaEventDisableTiming);
        cudaFuncSetAttribute(scores_kernel,
                             cudaFuncAttributeMaxDynamicSharedMemorySize, SC_TOTAL);
        cudaFuncSetAttribute(out_kernel,
                             cudaFuncAttributeMaxDynamicSharedMemorySize, OC_TOTAL);
    }

    pack_all<<<(BATCH * (CDIM / 2) * LDIM) / 256, 256>>>(q, k, v, sd);

    // group 0 scores on default stream
    scores_kernel<<<dim3(LDIM / 32, 16), T1, SC_TOTAL>>>(table, ridx, 0);
    cudaEventRecord(evA, 0);

    // group 1 scores continues on default stream
    scores_kernel<<<dim3(LDIM / 32, 16), T1, SC_TOTAL>>>(table, ridx, 16);

    // group 0 out on side stream, overlapping group 1 scores
    cudaStreamWaitEvent(s2, evA, 0);
    out_kernel<<<dim3(LDIM / 128, CDIM / 64, 16), T2, OC_TOTAL, s2>>>(out, 0);
    cudaEventRecord(evB, s2);

    // group 1 out on default stream, then join side stream
    out_kernel<<<dim3(LDIM / 128, CDIM / 64, 16), T2, OC_TOTAL>>>(out, 16);
    cudaStreamWaitEvent(0, evB, 0);
}

// round 15
// speedup vs baseline: 1.0508x; 1.0508x over previous
#include <cuda_runtime.h>
#include <cuda_fp16.h>

#define BATCH 32
#define CDIM  256
#define LDIM  1024

// ---------------------------------------------------------------------------
// Global scratch
// q/k packed: [b][m][i], m = c/2, uint2 = (hi2, lo2)
// v/std packed: [b][c][j2] half2 ; P: [b][i][j2] half2
// ---------------------------------------------------------------------------
__device__ uint2    d_qpk[(size_t)BATCH * (CDIM / 2) * LDIM];      // 32 MiB
__device__ uint2    d_kpk[(size_t)BATCH * (CDIM / 2) * LDIM];      // 32 MiB
__device__ unsigned d_vpk[(size_t)BATCH * CDIM * (LDIM / 2)];      // 16 MiB
__device__ unsigned d_spk[(size_t)BATCH * CDIM * (LDIM / 2)];      // 16 MiB
__device__ unsigned d_Ph [(size_t)BATCH * LDIM * (LDIM / 2)];      // 64 MiB

__device__ __forceinline__ unsigned pk2(__half a, __half b) {
    __half2 t = __halves2half2(a, b);
    return *reinterpret_cast<unsigned*>(&t);
}

__device__ __forceinline__ void mma16(float* c,
                                      unsigned a0, unsigned a1, unsigned a2, unsigned a3,
                                      unsigned b0, unsigned b1) {
    asm volatile(
        "mma.sync.aligned.m16n8k16.row.col.f32.f16.f16.f32 "
        "{%0,%1,%2,%3}, {%4,%5,%6,%7}, {%8,%9}, {%0,%1,%2,%3};\n"
        : "+f"(c[0]), "+f"(c[1]), "+f"(c[2]), "+f"(c[3])
        : "r"(a0), "r"(a1), "r"(a2), "r"(a3), "r"(b0), "r"(b1));
}

__device__ __forceinline__ void ldsm4(unsigned& r0, unsigned& r1,
                                      unsigned& r2, unsigned& r3, unsigned a) {
    asm volatile("ldmatrix.sync.aligned.m8n8.x4.shared.b16 {%0,%1,%2,%3}, [%4];"
                 : "=r"(r0), "=r"(r1), "=r"(r2), "=r"(r3) : "r"(a));
}

__device__ __forceinline__ void cp16(unsigned dst, const void* src) {
    asm volatile("cp.async.cg.shared.global [%0], [%1], 16;" :: "r"(dst), "l"(src));
}
__device__ __forceinline__ void cp4(unsigned dst, const void* src) {
    asm volatile("cp.async.ca.shared.global [%0], [%1], 4;" :: "r"(dst), "l"(src));
}
#define CP_COMMIT() asm volatile("cp.async.commit_group;")
#define CP_WAIT(N)  asm volatile("cp.async.wait_group %0;" :: "n"(N))

// ---------------------------------------------------------------------------
// Merged pack kernel (R13, unchanged)
// ---------------------------------------------------------------------------
__global__ void pack_all(const float* __restrict__ q, const float* __restrict__ k,
                         const float* __restrict__ v, const float* __restrict__ sd) {
    int gid = blockIdx.x * 256 + threadIdx.x;

    {
        int b   = gid >> 17;
        int rem = gid & 131071;
        int m   = rem >> 10;
        int i   = rem & 1023;
        size_t src = (size_t)b * CDIM * LDIM + (size_t)(2 * m) * LDIM + i;

        float x0 = q[src], x1 = q[src + LDIM];
        __half h0 = __float2half_rn(x0), h1 = __float2half_rn(x1);
        __half l0 = __float2half_rn(x0 - __half2float(h0));
        __half l1 = __float2half_rn(x1 - __half2float(h1));
        d_qpk[gid] = make_uint2(pk2(h0, h1), pk2(l0, l1));

        float y0 = k[src], y1 = k[src + LDIM];
        __half g0 = __float2half_rn(y0), g1 = __float2half_rn(y1);
        __half m0 = __float2half_rn(y0 - __half2float(g0));
        __half m1 = __float2half_rn(y1 - __half2float(g1));
        d_kpk[gid] = make_uint2(pk2(g0, g1), pk2(m0, m1));
    }

    {
        size_t src = (size_t)gid * 2;
        float2 t = *(const float2*)(v + src);
        d_vpk[gid] = pk2(__float2half_rn(t.x), __float2half_rn(t.y));
        float2 u = *(const float2*)(sd + src);
        d_spk[gid] = pk2(__float2half_rn(u.x), __float2half_rn(u.y));
    }
}

// ---------------------------------------------------------------------------
// Kernel 1: scores = Q^T K + bias (fp16x2 3-pass), softmax, P -> half2.
// R13 structure + A-ldsm hoisted above CP_WAIT (the one retained R14 change).
// ---------------------------------------------------------------------------
#define T1 512
#define SC_QH   0
#define SC_QL   16896
#define SC_KW   33792
#define SC_RED  173056
#define SC_TOTAL 175104

__global__ void __launch_bounds__(T1)
scores_kernel(const float* __restrict__ table, const int* __restrict__ ridx) {
    extern __shared__ unsigned char smraw[];
    const unsigned sbase = (unsigned)__cvta_generic_to_shared(smraw);

    const int b    = blockIdx.y;
    const int i0   = blockIdx.x * 32;
    const int tid  = threadIdx.x;
    const int warp = tid >> 5;
    const int lane = tid & 31;
    const int g    = lane >> 2;
    const int tig  = lane & 3;
    const int j0w  = warp * 64;

    const uint2* gq = d_qpk + (size_t)b * (CDIM / 2) * LDIM;
    const uint2* gk = d_kpk + (size_t)b * (CDIM / 2) * LDIM;

    float acc[2][8][4];
#pragma unroll
    for (int it = 0; it < 2; it++)
#pragma unroll
        for (int jt = 0; jt < 8; jt++)
#pragma unroll
            for (int f = 0; f < 4; f++) acc[it][jt][f] = 0.f;

    // ---- stage full Q once ----
#pragma unroll
    for (int t = 0; t < 8; t++) {
        int idx = tid + t * T1;
        int m   = idx >> 5;
        int ii  = idx & 31;
        const uint2* s = gq + (size_t)m * LDIM + i0 + ii;
        unsigned d = (unsigned)((ii * 132 + m) * 4);
        cp4(sbase + SC_QH + d, &s->x);
        cp4(sbase + SC_QL + d, &s->y);
    }
    CP_COMMIT();

    // ---- per-warp K staging, carried pointer ----
    const int krow = lane >> 2;
    const int kq4  = lane & 3;
    const unsigned wd0 = sbase + SC_KW + warp * (2 * 4352) + krow * 544 + kq4 * 16;
    const unsigned wd1 = wd0 + 4352;
    const uint2* kptr = gk + (size_t)krow * LDIM + j0w + kq4 * 2;

#define SC_STAGEW(PTR, DSTB)                                                  \
    {                                                                         \
        _Pragma("unroll")                                                     \
        for (int t = 0; t < 8; t++)                                           \
            cp16((DSTB) + t * 64, (PTR) + t * 8);                             \
        CP_COMMIT();                                                          \
    }

    SC_STAGEW(kptr, wd0); kptr += 8 * LDIM;
    SC_STAGEW(kptr, wd1); kptr += 8 * LDIM;
    CP_WAIT(2);                           // Q resident
    __syncthreads();                      // the ONLY pre-epilogue barrier

    const unsigned arow = (lane & 15);
    const unsigned acol = (lane >> 4) * 16;
    const uint2* wkb0 = (const uint2*)(smraw + SC_KW + warp * (2 * 4352));
    const uint2* wkb1 = (const uint2*)(smraw + SC_KW + warp * (2 * 4352) + 4352);

    for (int cc = 0; cc < 16; cc++) {
        // A fragments first: independent of pending K groups (hoisted)
        unsigned ah[2][4], al[2][4];
#pragma unroll
        for (int it = 0; it < 2; it++) {
            ldsm4(ah[it][0], ah[it][1], ah[it][2], ah[it][3],
                  sbase + SC_QH + (it * 16 + arow) * 528 + cc * 32 + acol);
            ldsm4(al[it][0], al[it][1], al[it][2], al[it][3],
                  sbase + SC_QL + (it * 16 + arow) * 528 + cc * 32 + acol);
        }

        if (cc < 15) { CP_WAIT(1); } else { CP_WAIT(0); }

        const uint2* wkb = (cc & 1) ? wkb1 : wkb0;
        // jh = 0
        uint2 y0a[4], y1a[4];
#pragma unroll
        for (int j4 = 0; j4 < 4; j4++) {
            int jcol = j4 * 8 + g;
            y0a[j4] = wkb[tig * 68 + jcol];
            y1a[j4] = wkb[(tig + 4) * 68 + jcol];
        }
#pragma unroll
        for (int j4 = 0; j4 < 4; j4++)
#pragma unroll
            for (int it = 0; it < 2; it++)
                mma16(acc[it][j4], ah[it][0], ah[it][1], ah[it][2], ah[it][3],
                      y0a[j4].x, y1a[j4].x);
#pragma unroll
        for (int j4 = 0; j4 < 4; j4++)
#pragma unroll
            for (int it = 0; it < 2; it++)
                mma16(acc[it][j4], ah[it][0], ah[it][1], ah[it][2], ah[it][3],
                      y0a[j4].y, y1a[j4].y);
#pragma unroll
        for (int j4 = 0; j4 < 4; j4++)
#pragma unroll
            for (int it = 0; it < 2; it++)
                mma16(acc[it][j4], al[it][0], al[it][1], al[it][2], al[it][3],
                      y0a[j4].x, y1a[j4].x);

        // jh = 1: reads first, then refill this buffer, then mma
        uint2 y0b[4], y1b[4];
#pragma unroll
        for (int j4 = 0; j4 < 4; j4++) {
            int jcol = 32 + j4 * 8 + g;
            y0b[j4] = wkb[tig * 68 + jcol];
            y1b[j4] = wkb[(tig + 4) * 68 + jcol];
        }
        if (cc + 2 < 16) {
            unsigned dcur = (cc & 1) ? wd1 : wd0;
            SC_STAGEW(kptr, dcur);
            kptr += 8 * LDIM;
        }

#pragma unroll
        for (int j4 = 0; j4 < 4; j4++)
#pragma unroll
            for (int it = 0; it < 2; it++)
                mma16(acc[it][4 + j4], ah[it][0], ah[it][1], ah[it][2], ah[it][3],
                      y0b[j4].x, y1b[j4].x);
#pragma unroll
        for (int j4 = 0; j4 < 4; j4++)
#pragma unroll
            for (int it = 0; it < 2; it++)
                mma16(acc[it][4 + j4], ah[it][0], ah[it][1], ah[it][2], ah[it][3],
                      y0b[j4].y, y1b[j4].y);
#pragma unroll
        for (int j4 = 0; j4 < 4; j4++)
#pragma unroll
            for (int it = 0; it < 2; it++)
                mma16(acc[it][4 + j4], al[it][0], al[it][1], al[it][2], al[it][3],
                      y0b[j4].x, y1b[j4].x);
    }

    float* red = (float*)(smraw + SC_RED);

    // ---- add bias via table[ridx] gather ----
#pragma unroll
    for (int it = 0; it < 2; it++)
#pragma unroll
        for (int rr = 0; rr < 2; rr++) {
            int rowl = it * 16 + g + rr * 8;
            const int* rrow = ridx + (size_t)(i0 + rowl) * LDIM + j0w + 2 * tig;
#pragma unroll
            for (int jt = 0; jt < 8; jt++) {
                int2 rv = *(const int2*)(rrow + jt * 8);
                acc[it][jt][rr * 2]     += __ldg(table + rv.x);
                acc[it][jt][rr * 2 + 1] += __ldg(table + rv.y);
            }
        }

    // ---- row max ----
    float mrow[2][2];
#pragma unroll
    for (int it = 0; it < 2; it++)
#pragma unroll
        for (int rr = 0; rr < 2; rr++) {
            float m = -3.4e38f;
#pragma unroll
            for (int jt = 0; jt < 8; jt++) {
                m = fmaxf(m, acc[it][jt][rr * 2]);
                m = fmaxf(m, acc[it][jt][rr * 2 + 1]);
            }
            m = fmaxf(m, __shfl_xor_sync(0xffffffffu, m, 1));
            m = fmaxf(m, __shfl_xor_sync(0xffffffffu, m, 2));
            if (tig == 0) red[(it * 16 + g + rr * 8) * 16 + warp] = m;
        }
    __syncthreads();
#pragma unroll
    for (int it = 0; it < 2; it++)
#pragma unroll
        for (int rr = 0; rr < 2; rr++) {
            int rowl = it * 16 + g + rr * 8;
            float m = red[rowl * 16];
#pragma unroll
            for (int w = 1; w < 16; w++) m = fmaxf(m, red[rowl * 16 + w]);
            mrow[it][rr] = m;
        }
    __syncthreads();

    // ---- exp + row sum ----
#pragma unroll
    for (int it = 0; it < 2; it++)
#pragma unroll
        for (int rr = 0; rr < 2; rr++) {
            float s = 0.f;
#pragma unroll
            for (int jt = 0; jt < 8; jt++) {
                float p0 = __expf(acc[it][jt][rr * 2]     - mrow[it][rr]);
                float p1 = __expf(acc[it][jt][rr * 2 + 1] - mrow[it][rr]);
                acc[it][jt][rr * 2]     = p0;
                acc[it][jt][rr * 2 + 1] = p1;
                s += p0 + p1;
            }
            s += __shfl_xor_sync(0xffffffffu, s, 1);
            s += __shfl_xor_sync(0xffffffffu, s, 2);
            if (tig == 0) red[(it * 16 + g + rr * 8) * 16 + warp] = s;
        }
    __syncthreads();

    unsigned* Pb = d_Ph + ((size_t)b * LDIM + i0) * (LDIM / 2);
#pragma unroll
    for (int it = 0; it < 2; it++)
#pragma unroll
        for (int rr = 0; rr < 2; rr++) {
            int rowl = it * 16 + g + rr * 8;
            float s = red[rowl * 16];
#pragma unroll
            for (int w = 1; w < 16; w++) s += red[rowl * 16 + w];
            float inv = 1.0f / s;
            unsigned* prow = Pb + (size_t)rowl * (LDIM / 2) + j0w / 2 + tig;
#pragma unroll
            for (int jt = 0; jt < 8; jt++) {
                __half2 h = __floats2half2_rn(acc[it][jt][rr * 2] * inv,
                                              acc[it][jt][rr * 2 + 1] * inv);
                prow[jt * 4] = *reinterpret_cast<unsigned*>(&h);
            }
        }
}

// ---------------------------------------------------------------------------
// Kernel 2: out (EXACT R13 version: full 32-batch grid, 3 bufs, 1 sync/chunk)
// ---------------------------------------------------------------------------
#define T2  256
#define OSW 36

#define OC_BUFB     ((128 + 64 + 64) * OSW * 4)
#define OC_PS(buf)  ((buf) * OC_BUFB)
#define OC_VS(buf)  (OC_PS(buf) + 128 * OSW * 4)
#define OC_SS(buf)  (OC_PS(buf) + (128 + 64) * OSW * 4)
#define OC_TOTAL    (3 * OC_BUFB)

__global__ void __launch_bounds__(T2, 2)
out_kernel(float* __restrict__ out) {
    extern __shared__ unsigned char smraw2[];
    const unsigned sbase = (unsigned)__cvta_generic_to_shared(smraw2);

    const int b    = blockIdx.z;
    const int i0   = blockIdx.x * 128;
    const int c0   = blockIdx.y * 64;
    const int tid  = threadIdx.x;
    const int warp = tid >> 5;
    const int lane = tid & 31;
    const int g    = lane >> 2;
    const int tig  = lane & 3;
    const int wi   = warp & 3;
    const int wc   = warp >> 2;

    const unsigned* Pb = d_Ph + ((size_t)b * LDIM + i0) * (LDIM / 2);
    const unsigned* vb = d_vpk + ((size_t)b * CDIM + c0) * (LDIM / 2);
    const unsigned* sb = d_spk + ((size_t)b * CDIM + c0) * (LDIM / 2);

    float aV[2][4][4], aS[2][4][4];
#pragma unroll
    for (int it = 0; it < 2; it++)
#pragma unroll
        for (int nt = 0; nt < 4; nt++)
#pragma unroll
            for (int f = 0; f < 4; f++) { aV[it][nt][f] = 0.f; aS[it][nt][f] = 0.f; }

#define OC_STAGE(JC, BUF)                                                     \
    {                                                                         \
        _Pragma("unroll")                                                     \
        for (int t = 0; t < 4; t++) {                                         \
            int idx  = tid + t * T2;                                          \
            int row  = idx >> 3;                                              \
            int col4 = idx & 7;                                               \
            cp16(sbase + OC_PS(BUF) + row * (OSW * 4) + col4 * 16,            \
                 Pb + (size_t)row * (LDIM / 2) + (JC) * 32 + col4 * 4);       \
        }                                                                     \
        _Pragma("unroll")                                                     \
        for (int t = 0; t < 2; t++) {                                         \
            int idx  = tid + t * T2;                                          \
            int row  = idx >> 3;                                              \
            int col4 = idx & 7;                                               \
            unsigned soff = row * (OSW * 4) + col4 * 16;                      \
            size_t   goff = (size_t)row * (LDIM / 2) + (JC) * 32 + col4 * 4;  \
            cp16(sbase + OC_VS(BUF) + soff, vb + goff);                       \
            cp16(sbase + OC_SS(BUF) + soff, sb + goff);                       \
        }                                                                     \
        CP_COMMIT();                                                          \
    }

    OC_STAGE(0, 0);
    OC_STAGE(1, 1);

    const unsigned a_row = (lane & 15);
    const unsigned a_col = (lane >> 4) * 16;
    const unsigned b_row = ((lane >> 4) & 1) * 8 + (lane & 7);
    const unsigned b_col = ((lane >> 3) & 1) * 16;

    int bufc = 0;
    int bufs = 2;
    for (int jc = 0; jc < 16; jc++) {
        if (jc < 15) { CP_WAIT(1); } else { CP_WAIT(0); }
        __syncthreads();

#pragma unroll
        for (int kb = 0; kb < 4; kb++) {
            unsigned a0[2], a1[2], a2[2], a3[2];
#pragma unroll
            for (int it = 0; it < 2; it++)
                ldsm4(a0[it], a1[it], a2[it], a3[it],
                      sbase + OC_PS(bufc) +
                      (wi * 32 + it * 16 + a_row) * (OSW * 4) + kb * 32 + a_col);

            unsigned bv0[4], bv1[4], bs0[4], bs1[4];
#pragma unroll
            for (int nh = 0; nh < 2; nh++) {
                unsigned roff = (wc * 32 + nh * 16 + b_row) * (OSW * 4) + kb * 32 + b_col;
                ldsm4(bv0[2 * nh], bv1[2 * nh], bv0[2 * nh + 1], bv1[2 * nh + 1],
                      sbase + OC_VS(bufc) + roff);
                ldsm4(bs0[2 * nh], bs1[2 * nh], bs0[2 * nh + 1], bs1[2 * nh + 1],
                      sbase + OC_SS(bufc) + roff);
            }
#pragma unroll
            for (int nt = 0; nt < 4; nt++)
#pragma unroll
                for (int it = 0; it < 2; it++) {
                    mma16(aV[it][nt], a0[it], a1[it], a2[it], a3[it], bv0[nt], bv1[nt]);
                    mma16(aS[it][nt], a0[it], a1[it], a2[it], a3[it], bs0[nt], bs1[nt]);
                }
        }
        if (jc + 2 < 16) OC_STAGE(jc + 2, bufs);
        bufc = (bufc == 2) ? 0 : bufc + 1;
        bufs = (bufs == 2) ? 0 : bufs + 1;
    }

    const size_t base  = (size_t)b * CDIM * LDIM;
    const size_t sdoff = (size_t)BATCH * CDIM * LDIM;
#pragma unroll
    for (int it = 0; it < 2; it++)
#pragma unroll
        for (int nt = 0; nt < 4; nt++)
#pragma unroll
            for (int rr = 0; rr < 2; rr++) {
                int i = i0 + wi * 32 + it * 16 + g + rr * 8;
#pragma unroll
                for (int ff = 0; ff < 2; ff++) {
                    int c = c0 + wc * 32 + nt * 8 + 2 * tig + ff;
                    size_t o = base + (size_t)c * LDIM + i;
                    out[o]         = aV[it][nt][rr * 2 + ff];
                    out[o + sdoff] = aS[it][nt][rr * 2 + ff];
                }
            }
}

// ---------------------------------------------------------------------------
// Launch: R13 single-stream structure.
// ---------------------------------------------------------------------------
extern "C" void kernel_launch(void* const* d_in, const int* in_sizes, int n_in,
                              void* d_out, int out_size) {
    const float* q     = (const float*)d_in[0];
    const float* k     = (const float*)d_in[1];
    const float* v     = (const float*)d_in[2];
    const float* sd    = (const float*)d_in[3];
    const float* table = (const float*)d_in[4];
    const int*   ridx  = (const int*)d_in[5];
    float* out = (float*)d_out;

    cudaFuncSetAttribute(scores_kernel, cudaFuncAttributeMaxDynamicSharedMemorySize, SC_TOTAL);
    cudaFuncSetAttribute(out_kernel,    cudaFuncAttributeMaxDynamicSharedMemorySize, OC_TOTAL);

    pack_all<<<(BATCH * (CDIM / 2) * LDIM) / 256, 256>>>(q, k, v, sd);
    scores_kernel<<<dim3(LDIM / 32, BATCH), T1, SC_TOTAL>>>(table, ridx);
    out_kernel<<<dim3(LDIM / 128, CDIM / 64, BATCH), T2, OC_TOTAL>>>(out);
}